// round 1
// baseline (speedup 1.0000x reference)
#include <cuda_runtime.h>
#include <cuda_bf16.h>
#include <stdint.h>

#define NROWS 8192
#define INP   512
#define NOUT  128
#define SLOPE 0.2f

// ---------------- device scratch (no allocations allowed) ----------------
__device__ float  g_Wh[NROWS * NOUT];        // 4 MB
__device__ float4 g_UV[NROWS * 64];          // 8 MB : per j, per colpair c: (U[2c],U[2c+1],V[2c],V[2c+1])
__device__ float  g_f1[NROWS];
__device__ float  g_f2[NROWS];
__device__ float  g_A[NROWS];                // e^{f1}
__device__ float  g_C[NROWS];                // e^{0.2 f1}
__device__ float  g_zinv[NROWS];
__device__ float2 g_uvs[NROWS];              // (e^{f2_j}, e^{0.2 f2_j})

// predicated packed fp32x2 add:  if (cond) acc += v   (two fp32 adds in one instr)
__device__ __forceinline__ void pfadd2(unsigned long long &acc, unsigned long long v, unsigned int cond) {
    asm("{\n\t"
        ".reg .pred p;\n\t"
        "setp.ne.u32 p, %2, 0;\n\t"
        "@p add.rn.f32x2 %0, %0, %1;\n\t"
        "}"
        : "+l"(acc) : "l"(v), "r"(cond));
}

// ---------------- K1: Wh = h @ W  (8192x512 @ 512x128, fp32) ----------------
__global__ __launch_bounds__(256) void k1_wh(const float* __restrict__ h, const float* __restrict__ W) {
    __shared__ float hs[32][33];
    __shared__ float Ws[32][128];
    const int t  = threadIdx.x;
    const int i0 = blockIdx.x * 32;
    const int tx = t & 31;        // 32 col-groups of 4
    const int ty = t >> 5;        // 8 row-groups of 4

    float acc[4][4];
#pragma unroll
    for (int r = 0; r < 4; r++)
#pragma unroll
        for (int c = 0; c < 4; c++) acc[r][c] = 0.f;

    for (int k0 = 0; k0 < INP; k0 += 32) {
        // stage h tile 32x32
        {
            int r  = t >> 3;
            int kc = (t & 7) * 4;
            float4 hv = *(const float4*)(h + (size_t)(i0 + r) * INP + k0 + kc);
            hs[r][kc] = hv.x; hs[r][kc + 1] = hv.y; hs[r][kc + 2] = hv.z; hs[r][kc + 3] = hv.w;
        }
        // stage W tile 32x128
#pragma unroll
        for (int q = 0; q < 4; q++) {
            int kr = (t >> 5) + q * 8;
            int cc = (t & 31) * 4;
            *(float4*)&Ws[kr][cc] = *(const float4*)(W + (size_t)(k0 + kr) * NOUT + cc);
        }
        __syncthreads();
#pragma unroll
        for (int kk = 0; kk < 32; kk++) {
            float4 bv = *(float4*)&Ws[kk][tx * 4];
            float a0 = hs[ty * 4 + 0][kk];
            float a1 = hs[ty * 4 + 1][kk];
            float a2 = hs[ty * 4 + 2][kk];
            float a3 = hs[ty * 4 + 3][kk];
            acc[0][0] += a0 * bv.x; acc[0][1] += a0 * bv.y; acc[0][2] += a0 * bv.z; acc[0][3] += a0 * bv.w;
            acc[1][0] += a1 * bv.x; acc[1][1] += a1 * bv.y; acc[1][2] += a1 * bv.z; acc[1][3] += a1 * bv.w;
            acc[2][0] += a2 * bv.x; acc[2][1] += a2 * bv.y; acc[2][2] += a2 * bv.z; acc[2][3] += a2 * bv.w;
            acc[3][0] += a3 * bv.x; acc[3][1] += a3 * bv.y; acc[3][2] += a3 * bv.z; acc[3][3] += a3 * bv.w;
        }
        __syncthreads();
    }
#pragma unroll
    for (int r = 0; r < 4; r++) {
        float4 o = make_float4(acc[r][0], acc[r][1], acc[r][2], acc[r][3]);
        *(float4*)&g_Wh[(size_t)(i0 + ty * 4 + r) * NOUT + tx * 4] = o;
    }
}

// ---------------- K2: f1,f2, exps, and interleaved UV array ----------------
__global__ __launch_bounds__(128) void k2_feats(const float* __restrict__ a) {
    const int warp = threadIdx.x >> 5;
    const int lane = threadIdx.x & 31;
    const int i = blockIdx.x * 4 + warp;
    const float* wh = g_Wh + (size_t)i * NOUT;

    float s1 = 0.f, s2 = 0.f;
#pragma unroll
    for (int q = 0; q < 4; q++) {
        int k = lane + q * 32;
        float w = wh[k];
        s1 += w * __ldg(&a[k]);
        s2 += w * __ldg(&a[128 + k]);
    }
#pragma unroll
    for (int off = 16; off > 0; off >>= 1) {
        s1 += __shfl_xor_sync(0xffffffffu, s1, off);
        s2 += __shfl_xor_sync(0xffffffffu, s2, off);
    }
    const float f1 = s1, f2 = s2;
    const float u = expf(f2);
    const float v = expf(SLOPE * f2);
    // colpairs c = lane and lane+32
#pragma unroll
    for (int q = 0; q < 2; q++) {
        int c = lane + q * 32;
        float2 p = ((const float2*)wh)[c];
        g_UV[(size_t)i * 64 + c] = make_float4(u * p.x, u * p.y, v * p.x, v * p.y);
    }
    if (lane == 0) {
        g_f1[i] = f1;
        g_f2[i] = f2;
        g_A[i]  = expf(f1);
        g_C[i]  = expf(SLOPE * f1);
        g_uvs[i] = make_float2(u, v);
    }
}

// ---------------- K3: softmax denominators Z_i -> g_zinv ----------------
__global__ __launch_bounds__(256) void k3_z(const int* __restrict__ adj) {
    const int warp = threadIdx.x >> 5;
    const int lane = threadIdx.x & 31;
    const int i = blockIdx.x * 8 + warp;
    const float f1 = g_f1[i];
    const int* arow = adj + (size_t)i * NROWS;

    float zu = 0.f, zv = 0.f;
    for (int j = lane; j < NROWS; j += 32) {
        int m = arow[j];
        if (m) {
            float f2 = __ldg(&g_f2[j]);
            float2 uvj = __ldg(&g_uvs[j]);
            if (f1 + f2 >= 0.f) zu += uvj.x; else zv += uvj.y;
        }
    }
#pragma unroll
    for (int off = 16; off > 0; off >>= 1) {
        zu += __shfl_xor_sync(0xffffffffu, zu, off);
        zv += __shfl_xor_sync(0xffffffffu, zv, off);
    }
    if (lane == 0) {
        float Z = g_A[i] * zu + g_C[i] * zv;
        g_zinv[i] = 1.0f / Z;
    }
}

// ---------------- K4: masked accumulation (the hot loop) ----------------
// 16 rows per CTA, 128 threads: t<64 -> rows 0..7, t>=64 -> rows 8..15; c = t&63 owns output cols {2c,2c+1}.
#define RJT 32
__global__ __launch_bounds__(128) void k4_main(const int* __restrict__ adj, float* __restrict__ out) {
    __shared__ ulonglong2 UVs[RJT * 64];   // 32 KB: per (j,c): .x=(U0,U1) .y=(V0,V1)
    __shared__ unsigned int adjs[16 * RJT];
    __shared__ unsigned int maskw[RJT];
    __shared__ float f1s[16];

    const int t = threadIdx.x;
    const int half = t >> 6;
    const int c = t & 63;
    const int i0 = blockIdx.x * 16;

    if (t < 16) f1s[t] = g_f1[i0 + t];

    unsigned long long acc1[8], acc2[8];
#pragma unroll
    for (int r = 0; r < 8; r++) { acc1[r] = 0ull; acc2[r] = 0ull; }

    const ulonglong2* gUV = (const ulonglong2*)g_UV;
    const int rstage = t >> 3;
    const int jstage = (t & 7) * 4;

    for (int jt = 0; jt < NROWS; jt += RJT) {
        // stage adj tile (16 x 32 int), exactly int4 per thread
        {
            int4 av = *(const int4*)(adj + (size_t)(i0 + rstage) * NROWS + jt + jstage);
            ((int4*)adjs)[t] = av;
        }
        // stage UV tile (32 j x 64 colpairs x 16B)
#pragma unroll
        for (int q = 0; q < 16; q++) {
            UVs[q * 128 + t] = gUV[(size_t)jt * 64 + q * 128 + t];
        }
        __syncthreads();
        // build packed mask words: bit r = adj&pos, bit 16+r = adj&neg
        if (t < RJT) {
            float f2j = __ldg(&g_f2[jt + t]);
            unsigned int w = 0u;
#pragma unroll
            for (int r = 0; r < 16; r++) {
                if (adjs[r * RJT + t])
                    w |= (f1s[r] + f2j >= 0.f) ? (1u << r) : (1u << (16 + r));
            }
            maskw[t] = w;
        }
        __syncthreads();
        // main accumulation
#pragma unroll 2
        for (int j = 0; j < RJT; j++) {
            ulonglong2 uv = UVs[j * 64 + c];
            unsigned int ws = maskw[j] >> (half * 8);
#pragma unroll
            for (int rr = 0; rr < 8; rr++) {
                pfadd2(acc1[rr], uv.x, ws & (1u << rr));
                pfadd2(acc2[rr], uv.y, ws & (1u << (16 + rr)));
            }
        }
        __syncthreads();
    }

    // epilogue: out[i][2c..2c+1] = (A_i*S1 + C_i*S2) * zinv_i
#pragma unroll
    for (int rr = 0; rr < 8; rr++) {
        int i = i0 + half * 8 + rr;
        float A  = __ldg(&g_A[i]);
        float Cc = __ldg(&g_C[i]);
        float zi = __ldg(&g_zinv[i]);
        float2 s1 = *(float2*)&acc1[rr];
        float2 s2 = *(float2*)&acc2[rr];
        float2 o;
        o.x = (A * s1.x + Cc * s2.x) * zi;
        o.y = (A * s1.y + Cc * s2.y) * zi;
        ((float2*)out)[(size_t)i * 64 + c] = o;
    }
}

// ---------------- launcher ----------------
extern "C" void kernel_launch(void* const* d_in, const int* in_sizes, int n_in,
                              void* d_out, int out_size) {
    // identify inputs by element count (robust against ordering)
    const float* h = nullptr; const int* adj = nullptr; const float* W = nullptr; const float* a = nullptr;
    for (int k = 0; k < n_in; k++) {
        switch (in_sizes[k]) {
            case NROWS * INP:          h   = (const float*)d_in[k]; break;
            case NROWS * NROWS:        adj = (const int*)d_in[k];   break;
            case INP * NOUT:           W   = (const float*)d_in[k]; break;
            case 2 * NOUT:             a   = (const float*)d_in[k]; break;
            default: break;
        }
    }
    float* out = (float*)d_out;

    k1_wh  <<<NROWS / 32, 256>>>(h, W);
    k2_feats<<<NROWS / 4, 128>>>(a);
    k3_z   <<<NROWS / 8, 256>>>(adj);
    k4_main<<<NROWS / 16, 128>>>(adj, out);
}

// round 3
// speedup vs baseline: 4.3872x; 4.3872x over previous
#include <cuda_runtime.h>
#include <cuda_bf16.h>
#include <stdint.h>

#define NROWS 8192
#define INP   512
#define NOUT  128
#define SLOPE 0.2f

// ---------------- device scratch ----------------
__device__ float  g_Wh[NROWS * NOUT];           // 4 MB
__device__ float  g_f1[NROWS];
__device__ float  g_f2[NROWS];
__device__ float  g_A[NROWS];
__device__ float  g_C[NROWS];
__device__ float  g_zinv[NROWS];
__device__ float2 g_uvs[NROWS];
__device__ unsigned int g_bits[NROWS * 256];    // 8 MB bitpacked adj
__device__ uint4  g_UVT4[4 * 128 * 1024];       // 8 MB : 4 matrices x 128 chunks x 16KB pre-swizzled B^T tiles
__device__ float  g_part[2 * NROWS * NOUT];     // 8 MB partials

// ---------------- helpers ----------------
__device__ __forceinline__ uint32_t smem_u32(const void* p) {
    uint32_t r;
    asm("{ .reg .u64 t; cvta.to.shared.u64 t, %1; cvt.u32.u64 %0, t; }" : "=r"(r) : "l"(p));
    return r;
}
#define SW128(x) ((x) ^ (((x) >> 3) & 0x70))

#define LDSM_X4(r0, r1, r2, r3, addr) \
    asm volatile("ldmatrix.sync.aligned.m8n8.x4.shared.b16 {%0,%1,%2,%3}, [%4];" \
        : "=r"(r0), "=r"(r1), "=r"(r2), "=r"(r3) : "r"(addr))

#define MMA16816(d, a0, a1, a2, a3, b0, b1) \
    asm volatile("mma.sync.aligned.m16n8k16.row.col.f32.bf16.bf16.f32 " \
        "{%0,%1,%2,%3},{%4,%5,%6,%7},{%8,%9},{%0,%1,%2,%3};" \
        : "+f"((d)[0]), "+f"((d)[1]), "+f"((d)[2]), "+f"((d)[3]) \
        : "r"(a0), "r"(a1), "r"(a2), "r"(a3), "r"(b0), "r"(b1))

__device__ __forceinline__ void cp_async16(uint32_t dst, const void* src) {
    asm volatile("cp.async.cg.shared.global [%0], [%1], 16;" :: "r"(dst), "l"(src) : "memory");
}
#define CP_COMMIT() asm volatile("cp.async.commit_group;" ::: "memory")
#define CP_WAIT1()  asm volatile("cp.async.wait_group 1;" ::: "memory")

// ---------------- K0: bitpack adj ----------------
__global__ __launch_bounds__(256) void k_pack(const int* __restrict__ adj) {
    const int i = blockIdx.x;
    const int w = threadIdx.x >> 5, lane = threadIdx.x & 31;
    const int* row = adj + (size_t)i * NROWS;
    for (int q = w; q < 256; q += 8) {
        int v = row[q * 32 + lane];
        unsigned m = __ballot_sync(0xffffffffu, v != 0);
        if (lane == 0) g_bits[(size_t)i * 256 + q] = m;
    }
}

// ---------------- K1: Wh = h @ W ----------------
__global__ __launch_bounds__(256) void k1_wh(const float* __restrict__ h, const float* __restrict__ W) {
    __shared__ float hs[32][33];
    __shared__ float Ws[32][128];
    const int t  = threadIdx.x;
    const int i0 = blockIdx.x * 32;
    const int tx = t & 31;
    const int ty = t >> 5;

    float acc[4][4];
#pragma unroll
    for (int r = 0; r < 4; r++)
#pragma unroll
        for (int c = 0; c < 4; c++) acc[r][c] = 0.f;

    for (int k0 = 0; k0 < INP; k0 += 32) {
        {
            int r  = t >> 3;
            int kc = (t & 7) * 4;
            float4 hv = *(const float4*)(h + (size_t)(i0 + r) * INP + k0 + kc);
            hs[r][kc] = hv.x; hs[r][kc + 1] = hv.y; hs[r][kc + 2] = hv.z; hs[r][kc + 3] = hv.w;
        }
#pragma unroll
        for (int q = 0; q < 4; q++) {
            int kr = (t >> 5) + q * 8;
            int cc = (t & 31) * 4;
            *(float4*)&Ws[kr][cc] = *(const float4*)(W + (size_t)(k0 + kr) * NOUT + cc);
        }
        __syncthreads();
#pragma unroll
        for (int kk = 0; kk < 32; kk++) {
            float4 bv = *(float4*)&Ws[kk][tx * 4];
            float a0 = hs[ty * 4 + 0][kk];
            float a1 = hs[ty * 4 + 1][kk];
            float a2 = hs[ty * 4 + 2][kk];
            float a3 = hs[ty * 4 + 3][kk];
            acc[0][0] += a0 * bv.x; acc[0][1] += a0 * bv.y; acc[0][2] += a0 * bv.z; acc[0][3] += a0 * bv.w;
            acc[1][0] += a1 * bv.x; acc[1][1] += a1 * bv.y; acc[1][2] += a1 * bv.z; acc[1][3] += a1 * bv.w;
            acc[2][0] += a2 * bv.x; acc[2][1] += a2 * bv.y; acc[2][2] += a2 * bv.z; acc[2][3] += a2 * bv.w;
            acc[3][0] += a3 * bv.x; acc[3][1] += a3 * bv.y; acc[3][2] += a3 * bv.z; acc[3][3] += a3 * bv.w;
        }
        __syncthreads();
    }
#pragma unroll
    for (int r = 0; r < 4; r++) {
        float4 o = make_float4(acc[r][0], acc[r][1], acc[r][2], acc[r][3]);
        *(float4*)&g_Wh[(size_t)(i0 + ty * 4 + r) * NOUT + tx * 4] = o;
    }
}

// ---------------- K2: features + pre-swizzled UVT B^T-tile images ----------------
__global__ __launch_bounds__(128) void k2_feats(const float* __restrict__ a) {
    const int warp = threadIdx.x >> 5;
    const int lane = threadIdx.x & 31;
    const int j = blockIdx.x * 4 + warp;
    const float* wh = g_Wh + (size_t)j * NOUT;

    float ws[4];
    float s1 = 0.f, s2 = 0.f;
#pragma unroll
    for (int q = 0; q < 4; q++) {
        int k = lane + q * 32;
        float w = wh[k];
        ws[q] = w;
        s1 += w * __ldg(&a[k]);
        s2 += w * __ldg(&a[128 + k]);
    }
#pragma unroll
    for (int off = 16; off > 0; off >>= 1) {
        s1 += __shfl_xor_sync(0xffffffffu, s1, off);
        s2 += __shfl_xor_sync(0xffffffffu, s2, off);
    }
    const float f1 = s1, f2 = s2;
    const float u = expf(f2);
    const float v = expf(SLOPE * f2);

    const int tile = j >> 6;     // j-chunk (64 wide)
    const int jl   = j & 63;
    char* base = (char*)g_UVT4 + (size_t)tile * 16384;
#pragma unroll
    for (int q = 0; q < 4; q++) {
        int c = lane + q * 32;
        float U = u * ws[q];
        float V = v * ws[q];
        __nv_bfloat16 Uh = __float2bfloat16(U);
        __nv_bfloat16 Ul = __float2bfloat16(U - __bfloat162float(Uh));
        __nv_bfloat16 Vh = __float2bfloat16(V);
        __nv_bfloat16 Vl = __float2bfloat16(V - __bfloat162float(Vh));
        unsigned off = SW128((unsigned)(c * 128 + jl * 2));
        *(__nv_bfloat16*)(base + off)                 = Uh;
        *(__nv_bfloat16*)(base + 2097152u + off)      = Ul;
        *(__nv_bfloat16*)(base + 2u * 2097152u + off) = Vh;
        *(__nv_bfloat16*)(base + 3u * 2097152u + off) = Vl;
    }
    if (lane == 0) {
        g_f1[j] = f1;
        g_f2[j] = f2;
        g_A[j]  = expf(f1);
        g_C[j]  = expf(SLOPE * f1);
        g_uvs[j] = make_float2(u, v);
    }
}

// ---------------- K3: Z_i from bitpacked adj ----------------
__global__ __launch_bounds__(256) void k3_z() {
    const int warp = threadIdx.x >> 5;
    const int lane = threadIdx.x & 31;
    const int i = blockIdx.x * 8 + warp;
    const float thr = -g_f1[i];   // same predicate form as K4 masks
    const unsigned* brow = g_bits + (size_t)i * 256;

    float zu = 0.f, zv = 0.f;
#pragma unroll
    for (int q = 0; q < 8; q++) {
        unsigned w = brow[q * 32 + lane];
        int j0 = (q * 32 + lane) * 32;
        while (w) {
            int b = __ffs(w) - 1;
            w &= w - 1;
            int j = j0 + b;
            float f2 = __ldg(&g_f2[j]);
            float2 uv = __ldg(&g_uvs[j]);
            if (f2 >= thr) zu += uv.x; else zv += uv.y;
        }
    }
#pragma unroll
    for (int off = 16; off > 0; off >>= 1) {
        zu += __shfl_xor_sync(0xffffffffu, zu, off);
        zv += __shfl_xor_sync(0xffffffffu, zv, off);
    }
    if (lane == 0) g_zinv[i] = 1.0f / (g_A[i] * zu + g_C[i] * zv);
}

// ---------------- K4: HMMA masked GEMMs ----------------
// grid 128 = 64 row-tiles(128 i) x 2 j-halves(4096 j). 512 threads = 16 warps (4x4).
// Per 64-j chunk: build pos/neg bf16 mask tiles [128i x 64j] (SW128), cp.async 4
// pre-swizzled B^T tiles [128c x 64j]; mma.sync m16n8k16 accumulates pos@ (Uhi,Ulo)
// and neg@(Vhi,Vlo) into 2 fp32 accumulator sets.
#define MASKBYTES 32768
#define BTILE     16384
#define BBUF      (4 * BTILE)                    // 64 KB
#define DYNSMEM   (MASKBYTES + 2 * BBUF)         // 160 KB

__global__ void __launch_bounds__(512, 1) k4_hmma() {
    extern __shared__ __align__(16) char dyn[];
    __shared__ float s_f1[128];
    __shared__ float s_f2[4096];

    const int tid  = threadIdx.x;
    const int wid  = tid >> 5;
    const int lane = tid & 31;
    const int rt = blockIdx.x >> 1;
    const int hh = blockIdx.x & 1;
    const int i0 = rt << 7;
    const int j0 = hh << 12;

    char* bbuf = dyn + MASKBYTES;
    const uint32_t mpos_u = smem_u32(dyn);
    const uint32_t mneg_u = mpos_u + 16384u;
    const uint32_t bbuf_u = mpos_u + MASKBYTES;

    if (tid < 128) s_f1[tid] = g_f1[i0 + tid];
    for (int q = tid; q < 4096; q += 512) s_f2[q] = g_f2[j0 + q];
    __syncthreads();

    // accumulators: dp = pos-stream (U), dn = neg-stream (V). [mt][nt][4]
    float dp[2][4][4], dn[2][4][4];
#pragma unroll
    for (int mt = 0; mt < 2; mt++)
#pragma unroll
        for (int nt = 0; nt < 4; nt++)
#pragma unroll
            for (int r = 0; r < 4; r++) { dp[mt][nt][r] = 0.f; dn[mt][nt][r] = 0.f; }

    const int warp_m = wid >> 2;
    const int warp_n = wid & 3;
    const int ib = warp_m << 5;
    const int cb = warp_n << 5;

    // ldmatrix per-lane bases
    const int ri0 = ib + (lane & 15);            // mt=0 row
    const int ri1 = ri0 + 16;                    // mt=1 row
    const uint32_t arow0 = (uint32_t)ri0 * 128u, asw0 = (uint32_t)(ri0 & 7) << 4;
    const uint32_t arow1 = (uint32_t)ri1 * 128u, asw1 = (uint32_t)(ri1 & 7) << 4;
    const uint32_t akh   = (uint32_t)(lane >> 4) << 4;   // 0 or 16
    const int cr = cb + lane;
    const uint32_t brow = (uint32_t)cr * 128u, bsw = (uint32_t)(cr & 7) << 4;

    // cp.async B-tile prefetch for chunk 0
    {
        const char* srcb = (const char*)g_UVT4 + (size_t)(hh << 6) * 16384;
#pragma unroll
        for (int pass = 0; pass < 8; pass++) {
            int u = tid + pass * 512;
            int m = u >> 10;
            uint32_t off = (uint32_t)(u & 1023) << 4;
            cp_async16(bbuf_u + (uint32_t)m * BTILE + off,
                       srcb + (size_t)m * 2097152 + off);
        }
        CP_COMMIT();
    }

    for (int t = 0; t < 64; t++) {
        // prefetch chunk t+1
        if (t < 63) {
            const char* srcb = (const char*)g_UVT4 + (size_t)((hh << 6) + t + 1) * 16384;
            const uint32_t dstb = bbuf_u + (uint32_t)((t + 1) & 1) * BBUF;
#pragma unroll
            for (int pass = 0; pass < 8; pass++) {
                int u = tid + pass * 512;
                int m = u >> 10;
                uint32_t off = (uint32_t)(u & 1023) << 4;
                cp_async16(dstb + (uint32_t)m * BTILE + off,
                           srcb + (size_t)m * 2097152 + off);
            }
        }
        CP_COMMIT();

        // ---- build pos/neg mask tiles for chunk t ----
        const int tch = t << 6;
#pragma unroll
        for (int un = 0; un < 2; un++) {
            const int unit = (tid << 1) | un;
            const int i  = unit >> 3;
            const int jl = (unit & 7) << 3;
            const unsigned wrd = g_bits[(size_t)(i0 + i) * 256 + (unsigned)((j0 + tch + jl) >> 5)];
            const unsigned bits8 = (wrd >> (jl & 31)) & 0xFFu;
            const float thr = -s_f1[i];
            const uint32_t rbase = (uint32_t)i * 128u;
            const uint32_t rsw   = (uint32_t)(i & 7) << 4;
#pragma unroll
            for (int p = 0; p < 4; p++) {
                const int jj = jl + (p << 1);
                const float fa = s_f2[tch + jj];
                const float fb = s_f2[tch + jj + 1];
                const unsigned b0 = (bits8 >> (p << 1)) & 1u;
                const unsigned b1 = (bits8 >> ((p << 1) + 1)) & 1u;
                const unsigned q0 = (fa >= thr) ? 1u : 0u;
                const unsigned q1 = (fb >= thr) ? 1u : 0u;
                const unsigned wp = ((b0 & q0)        ? 0x3F80u : 0u) | ((b1 & q1)        ? 0x3F800000u : 0u);
                const unsigned wn = ((b0 & (q0 ^ 1u)) ? 0x3F80u : 0u) | ((b1 & (q1 ^ 1u)) ? 0x3F800000u : 0u);
                const uint32_t off = rbase + (((uint32_t)(jj << 1)) ^ rsw);
                *(unsigned*)(dyn + off)           = wp;
                *(unsigned*)(dyn + 16384u + off)  = wn;
            }
        }

        CP_WAIT1();          // B tiles of chunk t resident
        __syncthreads();     // masks + B visible to all

        // ---- mma phase ----
        const uint32_t bufb = bbuf_u + (uint32_t)(t & 1) * BBUF;
#pragma unroll
        for (int ks = 0; ks < 4; ks++) {
            const uint32_t joff = ((uint32_t)ks << 5) | akh;
            uint32_t ap0[4], ap1[4], an0[4], an1[4];
            LDSM_X4(ap0[0], ap0[1], ap0[2], ap0[3], mpos_u + arow0 + (joff ^ asw0));
            LDSM_X4(ap1[0], ap1[1], ap1[2], ap1[3], mpos_u + arow1 + (joff ^ asw1));
            LDSM_X4(an0[0], an0[1], an0[2], an0[3], mneg_u + arow0 + (joff ^ asw0));
            LDSM_X4(an1[0], an1[1], an1[2], an1[3], mneg_u + arow1 + (joff ^ asw1));
#pragma unroll
            for (int part = 0; part < 4; part++) {
                uint32_t b0[4], b1[4];
                const uint32_t pb = bufb + (uint32_t)part * BTILE + brow;
                LDSM_X4(b0[0], b0[1], b0[2], b0[3], pb + ((((uint32_t)ks << 5) | 0u)  ^ bsw));
                LDSM_X4(b1[0], b1[1], b1[2], b1[3], pb + ((((uint32_t)ks << 5) | 16u) ^ bsw));
                if (part < 2) {
#pragma unroll
                    for (int nt = 0; nt < 4; nt++) {
                        MMA16816(dp[0][nt], ap0[0], ap0[1], ap0[2], ap0[3], b0[nt], b1[nt]);
                        MMA16816(dp[1][nt], ap1[0], ap1[1], ap1[2], ap1[3], b0[nt], b1[nt]);
                    }
                } else {
#pragma unroll
                    for (int nt = 0; nt < 4; nt++) {
                        MMA16816(dn[0][nt], an0[0], an0[1], an0[2], an0[3], b0[nt], b1[nt]);
                        MMA16816(dn[1][nt], an1[0], an1[1], an1[2], an1[3], b0[nt], b1[nt]);
                    }
                }
            }
        }
        __syncthreads();     // protect masks before next build
    }

    // ---- epilogue: scale + write partial ----
    float* dst = g_part + (size_t)hh * (NROWS * NOUT);
#pragma unroll
    for (int mt = 0; mt < 2; mt++) {
        const int r0 = i0 + ib + mt * 16 + (lane >> 2);
        const int r1 = r0 + 8;
        const float A0 = g_A[r0], C0 = g_C[r0], z0 = g_zinv[r0];
        const float A1 = g_A[r1], C1 = g_C[r1], z1 = g_zinv[r1];
#pragma unroll
        for (int nt = 0; nt < 4; nt++) {
            const int c = cb + nt * 8 + ((lane & 3) << 1);
            float2 o0, o1;
            o0.x = (A0 * dp[mt][nt][0] + C0 * dn[mt][nt][0]) * z0;
            o0.y = (A0 * dp[mt][nt][1] + C0 * dn[mt][nt][1]) * z0;
            o1.x = (A1 * dp[mt][nt][2] + C1 * dn[mt][nt][2]) * z1;
            o1.y = (A1 * dp[mt][nt][3] + C1 * dn[mt][nt][3]) * z1;
            *(float2*)&dst[(size_t)r0 * NOUT + c] = o0;
            *(float2*)&dst[(size_t)r1 * NOUT + c] = o1;
        }
    }
}

// ---------------- K5: combine the two j-half partials ----------------
__global__ __launch_bounds__(256) void k_comb(float* __restrict__ out) {
    const int idx = blockIdx.x * 256 + threadIdx.x;
    const float4* p0 = (const float4*)g_part;
    const float4* p1 = (const float4*)(g_part + (size_t)NROWS * NOUT);
    float4 a = p0[idx], b = p1[idx];
    ((float4*)out)[idx] = make_float4(a.x + b.x, a.y + b.y, a.z + b.z, a.w + b.w);
}

// ---------------- launcher ----------------
extern "C" void kernel_launch(void* const* d_in, const int* in_sizes, int n_in,
                              void* d_out, int out_size) {
    const float* h = nullptr; const int* adj = nullptr; const float* W = nullptr; const float* a = nullptr;
    for (int k = 0; k < n_in; k++) {
        switch (in_sizes[k]) {
            case NROWS * INP:   h   = (const float*)d_in[k]; break;
            case NROWS * NROWS: adj = (const int*)d_in[k];   break;
            case INP * NOUT:    W   = (const float*)d_in[k]; break;
            case 2 * NOUT:      a   = (const float*)d_in[k]; break;
            default: break;
        }
    }
    float* out = (float*)d_out;

    static bool attr_done = false;
    if (!attr_done) {
        cudaFuncSetAttribute(k4_hmma, cudaFuncAttributeMaxDynamicSharedMemorySize, DYNSMEM);
        attr_done = true;
    }

    k_pack  <<<NROWS, 256>>>(adj);
    k1_wh   <<<NROWS / 32, 256>>>(h, W);
    k2_feats<<<NROWS / 4, 128>>>(a);
    k3_z    <<<NROWS / 8, 256>>>();
    k4_hmma <<<128, 512, DYNSMEM>>>();
    k_comb  <<<(NROWS * NOUT) / (256 * 4), 256>>>(out);
}

// round 6
// speedup vs baseline: 5.8645x; 1.3368x over previous
#include <cuda_runtime.h>
#include <cuda_bf16.h>
#include <stdint.h>

#define NROWS 8192
#define INP   512
#define NOUT  128
#define SLOPE 0.2f

// ---------------- device scratch ----------------
__device__ float  g_f1[NROWS];
__device__ float  g_f2[NROWS];
__device__ float  g_A[NROWS];
__device__ float  g_C[NROWS];
__device__ unsigned int g_bits[NROWS * 256];    // 8 MB bitpacked adj
__device__ uint4  g_UVT4[4 * 128 * 1024];       // 8 MB: 4 matrices x 128 chunks x 16KB pre-swizzled B^T tiles
__device__ uint4  g_ZT4[128 * 64];              // 128 KB: per chunk, 8 rows x 64 j bf16 (u_hi,u_lo,v_hi,v_lo,0..)
__device__ float  g_pp[2 * NROWS * NOUT];       // pos-stream partials (per j-half)
__device__ float  g_pn[2 * NROWS * NOUT];       // neg-stream partials
__device__ float  g_zu[2 * NROWS];
__device__ float  g_zv[2 * NROWS];
__device__ unsigned int g_cnt;                  // ticket barrier (monotonic)

// ---------------- helpers ----------------
__device__ __forceinline__ uint32_t smem_u32(const void* p) {
    uint32_t r;
    asm("{ .reg .u64 t; cvta.to.shared.u64 t, %1; cvt.u32.u64 %0, t; }" : "=r"(r) : "l"(p));
    return r;
}
#define SW128(x) ((x) ^ (((x) >> 3) & 0x70))

#define LDSM_X4(r0, r1, r2, r3, addr) \
    asm volatile("ldmatrix.sync.aligned.m8n8.x4.shared.b16 {%0,%1,%2,%3}, [%4];" \
        : "=r"(r0), "=r"(r1), "=r"(r2), "=r"(r3) : "r"(addr))

#define MMA16816(d, a0, a1, a2, a3, b0, b1) \
    asm volatile("mma.sync.aligned.m16n8k16.row.col.f32.bf16.bf16.f32 " \
        "{%0,%1,%2,%3},{%4,%5,%6,%7},{%8,%9},{%0,%1,%2,%3};" \
        : "+f"((d)[0]), "+f"((d)[1]), "+f"((d)[2]), "+f"((d)[3]) \
        : "r"(a0), "r"(a1), "r"(a2), "r"(a3), "r"(b0), "r"(b1))

__device__ __forceinline__ void cp_async16(uint32_t dst, const void* src) {
    asm volatile("cp.async.cg.shared.global [%0], [%1], 16;" :: "r"(dst), "l"(src) : "memory");
}
#define CP_COMMIT() asm volatile("cp.async.commit_group;" ::: "memory")
#define CP_WAIT1()  asm volatile("cp.async.wait_group 1;" ::: "memory")

__device__ __forceinline__ unsigned pack_bf16x2(float lo, float hi) {
    unsigned r;
    asm("cvt.rn.bf16x2.f32 %0, %1, %2;" : "=r"(r) : "f"(hi), "f"(lo));
    return r;
}

// ============ kA: fused [bitpack adj] + [Wh GEMM + features + UVT/ZT production] ============
// blocks [0,128): GEMM path, 64 rows each. blocks [128, 128+8192): pack one adj row.
__global__ __launch_bounds__(256) void kA(const float* __restrict__ h, const float* __restrict__ W,
                                          const float* __restrict__ a, const int* __restrict__ adj) {
    if (blockIdx.x >= 128) {
        const int i = blockIdx.x - 128;
        const int w = threadIdx.x >> 5, lane = threadIdx.x & 31;
        const int* row = adj + (size_t)i * NROWS;
#pragma unroll
        for (int q = 0; q < 32; q++) {          // 32 iters x 8 warps = 256 words
            int widx = w + q * 8;
            int v = row[widx * 32 + lane];
            unsigned m = __ballot_sync(0xffffffffu, v != 0);
            if (lane == 0) g_bits[(size_t)i * 256 + widx] = m;
        }
        return;
    }

    __shared__ float hs[64][33];
    __shared__ float Ws[32][128];
    const int t  = threadIdx.x;
    const int i0 = blockIdx.x * 64;
    const int tx = t & 31;          // lane
    const int ty = t >> 5;          // warp: rows ty*8 .. ty*8+7

    float acc[8][4];
#pragma unroll
    for (int r = 0; r < 8; r++)
#pragma unroll
        for (int c = 0; c < 4; c++) acc[r][c] = 0.f;

    for (int k0 = 0; k0 < INP; k0 += 32) {
#pragma unroll
        for (int p = 0; p < 2; p++) {
            int u = t + p * 256;
            int r = u >> 3, kc = (u & 7) * 4;
            float4 hv = *(const float4*)(h + (size_t)(i0 + r) * INP + k0 + kc);
            hs[r][kc] = hv.x; hs[r][kc + 1] = hv.y; hs[r][kc + 2] = hv.z; hs[r][kc + 3] = hv.w;
        }
#pragma unroll
        for (int p = 0; p < 4; p++) {
            int u = t + p * 256;
            int kr = u >> 5, cc = (u & 31) * 4;
            *(float4*)&Ws[kr][cc] = *(const float4*)(W + (size_t)(k0 + kr) * NOUT + cc);
        }
        __syncthreads();
#pragma unroll
        for (int kk = 0; kk < 32; kk++) {
            float4 bv = *(float4*)&Ws[kk][tx * 4];
#pragma unroll
            for (int r = 0; r < 8; r++) {
                float av = hs[ty * 8 + r][kk];
                acc[r][0] += av * bv.x; acc[r][1] += av * bv.y;
                acc[r][2] += av * bv.z; acc[r][3] += av * bv.w;
            }
        }
        __syncthreads();
    }

    // ---- f1/f2 per row (warp reduction over 128 cols) ----
    float4 a1 = __ldg((const float4*)(a + tx * 4));
    float4 a2 = __ldg((const float4*)(a + 128 + tx * 4));
    float uu[8], vv[8];
#pragma unroll
    for (int r = 0; r < 8; r++) {
        float s1 = acc[r][0] * a1.x + acc[r][1] * a1.y + acc[r][2] * a1.z + acc[r][3] * a1.w;
        float s2 = acc[r][0] * a2.x + acc[r][1] * a2.y + acc[r][2] * a2.z + acc[r][3] * a2.w;
#pragma unroll
        for (int off = 16; off > 0; off >>= 1) {
            s1 += __shfl_xor_sync(0xffffffffu, s1, off);
            s2 += __shfl_xor_sync(0xffffffffu, s2, off);
        }
        uu[r] = expf(s2);
        vv[r] = expf(SLOPE * s2);
        if (tx == r) {
            int j = i0 + ty * 8 + r;
            g_f1[j] = s1;
            g_f2[j] = s2;
            g_A[j]  = expf(s1);
            g_C[j]  = expf(SLOPE * s1);
        }
    }

    // ---- UVT writes: hi/lo split, row pairs packed into 4B stores ----
    const int jbase = ty * 8;  // j-local in chunk (chunk = blockIdx.x)
    char* base = (char*)g_UVT4 + (size_t)blockIdx.x * 16384;
#pragma unroll
    for (int rp = 0; rp < 4; rp++) {
#pragma unroll
        for (int c = 0; c < 4; c++) {
            float U0 = uu[2 * rp] * acc[2 * rp][c],     U1 = uu[2 * rp + 1] * acc[2 * rp + 1][c];
            float V0 = vv[2 * rp] * acc[2 * rp][c],     V1 = vv[2 * rp + 1] * acc[2 * rp + 1][c];
            float U0h = __bfloat162float(__float2bfloat16(U0));
            float U1h = __bfloat162float(__float2bfloat16(U1));
            float V0h = __bfloat162float(__float2bfloat16(V0));
            float V1h = __bfloat162float(__float2bfloat16(V1));
            unsigned off = SW128((unsigned)((tx * 4 + c) * 128 + (jbase + 2 * rp) * 2));
            *(unsigned*)(base + off)                 = pack_bf16x2(U0h, U1h);
            *(unsigned*)(base + 2097152u + off)      = pack_bf16x2(U0 - U0h, U1 - U1h);
            *(unsigned*)(base + 2u * 2097152u + off) = pack_bf16x2(V0h, V1h);
            *(unsigned*)(base + 3u * 2097152u + off) = pack_bf16x2(V0 - V0h, V1 - V1h);
        }
    }

    // ---- ZT writes: rows 0..3 = u_hi,u_lo,v_hi,v_lo over j; rows 4..7 zero ----
    {
        char* zb = (char*)g_ZT4 + (size_t)blockIdx.x * 1024;
        int rsel = tx & 7;
        float us = uu[0], vs = vv[0];
#pragma unroll
        for (int r = 1; r < 8; r++) if (rsel == r) { us = uu[r]; vs = vv[r]; }
        float uh = __bfloat162float(__float2bfloat16(us));
        float vh = __bfloat162float(__float2bfloat16(vs));
        int n = tx >> 3;  // 0..3
        float val = (n == 0) ? uh : (n == 1) ? (us - uh) : (n == 2) ? vh : (vs - vh);
        unsigned off = (unsigned)(n * 128) + (((unsigned)((jbase + rsel) * 2)) ^ ((unsigned)(n & 7) << 4));
        *(__nv_bfloat16*)(zb + off) = __float2bfloat16(val);
        if (t < 128) {
            int zn = 4 + (t >> 5);
            unsigned zoff = (unsigned)(zn * 128) + ((((unsigned)(t & 31)) * 4u) ^ ((unsigned)(zn & 7) << 4));
            *(unsigned*)(zb + zoff) = 0u;
        }
    }
}

// ============ K4: HMMA masked GEMMs + Z streams + device-wide combine ============
#define MASKBYTES 32768
#define BTILE     16384
#define ZTB       1024
#define BBUF      (4 * BTILE + ZTB)              // 66560
#define DYNSMEM   (MASKBYTES + 2 * BBUF)         // 165888

__global__ void __launch_bounds__(512, 1) k4_hmma(float* __restrict__ out) {
    extern __shared__ __align__(16) char dyn[];
    __shared__ float s_f1[128];
    __shared__ float s_f2[4096];

    const int tid  = threadIdx.x;
    const int wid  = tid >> 5;
    const int lane = tid & 31;
    const int rt = blockIdx.x >> 1;
    const int hh = blockIdx.x & 1;
    const int i0 = rt << 7;
    const int j0 = hh << 12;

    const uint32_t mpos_u = smem_u32(dyn);
    const uint32_t mneg_u = mpos_u + 16384u;
    const uint32_t bbuf_u = mpos_u + MASKBYTES;

    if (tid < 128) s_f1[tid] = g_f1[i0 + tid];
    for (int q = tid; q < 4096; q += 512) s_f2[q] = g_f2[j0 + q];
    __syncthreads();

    float dp[2][4][4], dn[2][4][4];
    float dzp[2][4], dzn[2][4];
#pragma unroll
    for (int mt = 0; mt < 2; mt++) {
#pragma unroll
        for (int nt = 0; nt < 4; nt++)
#pragma unroll
            for (int r = 0; r < 4; r++) { dp[mt][nt][r] = 0.f; dn[mt][nt][r] = 0.f; }
#pragma unroll
        for (int r = 0; r < 4; r++) { dzp[mt][r] = 0.f; dzn[mt][r] = 0.f; }
    }

    const int warp_m = wid >> 2;
    const int warp_n = wid & 3;
    const bool diag = (warp_m == warp_n);
    const int ib = warp_m << 5;
    const int cb = warp_n << 5;

    const int ri0 = ib + (lane & 15);
    const int ri1 = ri0 + 16;
    const uint32_t arow0 = (uint32_t)ri0 * 128u, asw0 = (uint32_t)(ri0 & 7) << 4;
    const uint32_t arow1 = (uint32_t)ri1 * 128u, asw1 = (uint32_t)(ri1 & 7) << 4;
    const uint32_t akh   = (uint32_t)(lane >> 4) << 4;
    const int cr = cb + lane;
    const uint32_t brow = (uint32_t)cr * 128u, bsw = (uint32_t)(cr & 7) << 4;

    // Z-fragment per-lane addressing (n = lane>>2 row, k-pair = (lane&3)*2)
    const uint32_t zn   = (uint32_t)(lane >> 2);
    const uint32_t zsw  = (zn & 7u) << 4;
    const uint32_t zrow = 4u * BTILE + zn * 128u;
    const uint32_t zkb  = ((uint32_t)(lane & 3)) << 2;

    // prefetch chunk 0 (B tiles + Z tile)
    {
        const char* srcb = (const char*)g_UVT4 + (size_t)(hh << 6) * 16384;
#pragma unroll
        for (int pass = 0; pass < 8; pass++) {
            int u = tid + pass * 512;
            int m = u >> 10;
            uint32_t off = (uint32_t)(u & 1023) << 4;
            cp_async16(bbuf_u + (uint32_t)m * BTILE + off, srcb + (size_t)m * 2097152 + off);
        }
        if (tid < 64)
            cp_async16(bbuf_u + 4u * BTILE + (uint32_t)tid * 16u,
                       (const char*)g_ZT4 + (size_t)(hh << 6) * 1024 + tid * 16);
        CP_COMMIT();
    }

    for (int t = 0; t < 64; t++) {
        if (t < 63) {
            const int nc = (hh << 6) + t + 1;
            const char* srcb = (const char*)g_UVT4 + (size_t)nc * 16384;
            const uint32_t dstb = bbuf_u + (uint32_t)((t + 1) & 1) * BBUF;
#pragma unroll
            for (int pass = 0; pass < 8; pass++) {
                int u = tid + pass * 512;
                int m = u >> 10;
                uint32_t off = (uint32_t)(u & 1023) << 4;
                cp_async16(dstb + (uint32_t)m * BTILE + off, srcb + (size_t)m * 2097152 + off);
            }
            if (tid < 64)
                cp_async16(dstb + 4u * BTILE + (uint32_t)tid * 16u,
                           (const char*)g_ZT4 + (size_t)nc * 1024 + tid * 16);
        }
        CP_COMMIT();

        // ---- build pos/neg mask tiles ----
        const int tch = t << 6;
#pragma unroll
        for (int un = 0; un < 2; un++) {
            const int unit = (tid << 1) | un;
            const int i  = unit >> 3;
            const int jl = (unit & 7) << 3;
            const unsigned wrd = g_bits[(size_t)(i0 + i) * 256 + (unsigned)((j0 + tch + jl) >> 5)];
            const unsigned bits8 = (wrd >> (jl & 31)) & 0xFFu;
            const float thr = -s_f1[i];
            const uint32_t rbase = (uint32_t)i * 128u;
            const uint32_t rsw   = (uint32_t)(i & 7) << 4;
#pragma unroll
            for (int p = 0; p < 4; p++) {
                const int jj = jl + (p << 1);
                const float fa = s_f2[tch + jj];
                const float fb = s_f2[tch + jj + 1];
                const unsigned b0 = (bits8 >> (p << 1)) & 1u;
                const unsigned b1 = (bits8 >> ((p << 1) + 1)) & 1u;
                const unsigned q0 = (fa >= thr) ? 1u : 0u;
                const unsigned q1 = (fb >= thr) ? 1u : 0u;
                const unsigned wp = ((b0 & q0)        ? 0x3F80u : 0u) | ((b1 & q1)        ? 0x3F800000u : 0u);
                const unsigned wn = ((b0 & (q0 ^ 1u)) ? 0x3F80u : 0u) | ((b1 & (q1 ^ 1u)) ? 0x3F800000u : 0u);
                const uint32_t off = rbase + (((uint32_t)(jj << 1)) ^ rsw);
                *(unsigned*)(dyn + off)          = wp;
                *(unsigned*)(dyn + 16384u + off) = wn;
            }
        }

        CP_WAIT1();
        __syncthreads();

        // ---- MMA phase ----
        const uint32_t bufb = bbuf_u + (uint32_t)(t & 1) * BBUF;
#pragma unroll
        for (int ks = 0; ks < 4; ks++) {
            const uint32_t joff = ((uint32_t)ks << 5) | akh;
            uint32_t ap0[4], ap1[4], an0[4], an1[4];
            LDSM_X4(ap0[0], ap0[1], ap0[2], ap0[3], mpos_u + arow0 + (joff ^ asw0));
            LDSM_X4(ap1[0], ap1[1], ap1[2], ap1[3], mpos_u + arow1 + (joff ^ asw1));
            LDSM_X4(an0[0], an0[1], an0[2], an0[3], mneg_u + arow0 + (joff ^ asw0));
            LDSM_X4(an1[0], an1[1], an1[2], an1[3], mneg_u + arow1 + (joff ^ asw1));
#pragma unroll
            for (int part = 0; part < 4; part++) {
                uint32_t b0[4], b1[4];
                const uint32_t pb = bufb + (uint32_t)part * BTILE + brow;
                LDSM_X4(b0[0], b0[1], b0[2], b0[3], pb + ((((uint32_t)ks << 5) | 0u)  ^ bsw));
                LDSM_X4(b1[0], b1[1], b1[2], b1[3], pb + ((((uint32_t)ks << 5) | 16u) ^ bsw));
                if (part < 2) {
#pragma unroll
                    for (int nt = 0; nt < 4; nt++) {
                        MMA16816(dp[0][nt], ap0[0], ap0[1], ap0[2], ap0[3], b0[nt], b1[nt]);
                        MMA16816(dp[1][nt], ap1[0], ap1[1], ap1[2], ap1[3], b0[nt], b1[nt]);
                    }
                } else {
#pragma unroll
                    for (int nt = 0; nt < 4; nt++) {
                        MMA16816(dn[0][nt], an0[0], an0[1], an0[2], an0[3], b0[nt], b1[nt]);
                        MMA16816(dn[1][nt], an1[0], an1[1], an1[2], an1[3], b0[nt], b1[nt]);
                    }
                }
            }
            // ---- Z-stream MMAs (diagonal warps only; one per SMSP) ----
            if (diag) {
                const uint32_t zk = ((uint32_t)ks << 5) + zkb;      // byte offset of k-pair
                const uint32_t a0 = bufb + zrow + (zk ^ zsw);
                const uint32_t a1 = bufb + zrow + ((zk + 16u) ^ zsw);
                uint32_t bz0, bz1;
                asm volatile("ld.shared.b32 %0, [%1];" : "=r"(bz0) : "r"(a0));
                asm volatile("ld.shared.b32 %0, [%1];" : "=r"(bz1) : "r"(a1));
                MMA16816(dzp[0], ap0[0], ap0[1], ap0[2], ap0[3], bz0, bz1);
                MMA16816(dzp[1], ap1[0], ap1[1], ap1[2], ap1[3], bz0, bz1);
                MMA16816(dzn[0], an0[0], an0[1], an0[2], an0[3], bz0, bz1);
                MMA16816(dzn[1], an1[0], an1[1], an1[2], an1[3], bz0, bz1);
            }
        }
        __syncthreads();
    }

    // ---- write raw partials ----
    float* pdst = g_pp + (size_t)hh * (NROWS * NOUT);
    float* ndst = g_pn + (size_t)hh * (NROWS * NOUT);
#pragma unroll
    for (int mt = 0; mt < 2; mt++) {
        const int r0 = i0 + ib + mt * 16 + (lane >> 2);
        const int r1 = r0 + 8;
#pragma unroll
        for (int nt = 0; nt < 4; nt++) {
            const int c = cb + nt * 8 + ((lane & 3) << 1);
            *(float2*)&pdst[(size_t)r0 * NOUT + c] = make_float2(dp[mt][nt][0], dp[mt][nt][1]);
            *(float2*)&pdst[(size_t)r1 * NOUT + c] = make_float2(dp[mt][nt][2], dp[mt][nt][3]);
            *(float2*)&ndst[(size_t)r0 * NOUT + c] = make_float2(dn[mt][nt][0], dn[mt][nt][1]);
            *(float2*)&ndst[(size_t)r1 * NOUT + c] = make_float2(dn[mt][nt][2], dn[mt][nt][3]);
        }
    }
    if (diag) {
#pragma unroll
        for (int mt = 0; mt < 2; mt++) {
            const int r0 = i0 + ib + mt * 16 + (lane >> 2);
            if ((lane & 3) == 0) {        // cols 0,1 = u_hi,u_lo
                g_zu[hh * NROWS + r0]     = dzp[mt][0] + dzp[mt][1];
                g_zu[hh * NROWS + r0 + 8] = dzp[mt][2] + dzp[mt][3];
            }
            if ((lane & 3) == 1) {        // cols 2,3 = v_hi,v_lo
                g_zv[hh * NROWS + r0]     = dzn[mt][0] + dzn[mt][1];
                g_zv[hh * NROWS + r0 + 8] = dzn[mt][2] + dzn[mt][3];
            }
        }
    }

    // ---- device-wide barrier (grid=128, 1 CTA/SM: all resident) ----
    __threadfence();
    __syncthreads();
    if (tid == 0) {
        unsigned t0 = atomicAdd(&g_cnt, 1u);
        unsigned target = ((t0 >> 7) + 1u) << 7;
        unsigned cur;
        do {
            asm volatile("ld.acquire.gpu.u32 %0, [%1];" : "=r"(cur) : "l"(&g_cnt));
            if (cur < target) __nanosleep(128);
        } while (cur < target);
    }
    __syncthreads();

    // ---- combine: this CTA normalizes rows [bid*64, bid*64+64) ----
    {
        const int rbase = blockIdx.x * 64;
#pragma unroll
        for (int it = 0; it < 4; it++) {
            int u = tid + it * 512;
            int r = rbase + (u >> 5);
            int c = (u & 31) * 4;
            float A = g_A[r], Cc = g_C[r];
            float z = A * (g_zu[r] + g_zu[NROWS + r]) + Cc * (g_zv[r] + g_zv[NROWS + r]);
            float zi = 1.f / z;
            const float4 p0 = *(const float4*)&g_pp[(size_t)r * NOUT + c];
            const float4 p1 = *(const float4*)&g_pp[(size_t)(NROWS + r) * NOUT + c];
            const float4 n0 = *(const float4*)&g_pn[(size_t)r * NOUT + c];
            const float4 n1 = *(const float4*)&g_pn[(size_t)(NROWS + r) * NOUT + c];
            float4 o;
            o.x = (A * (p0.x + p1.x) + Cc * (n0.x + n1.x)) * zi;
            o.y = (A * (p0.y + p1.y) + Cc * (n0.y + n1.y)) * zi;
            o.z = (A * (p0.z + p1.z) + Cc * (n0.z + n1.z)) * zi;
            o.w = (A * (p0.w + p1.w) + Cc * (n0.w + n1.w)) * zi;
            *(float4*)&out[(size_t)r * NOUT + c] = o;
        }
    }
}

// ---------------- launcher ----------------
extern "C" void kernel_launch(void* const* d_in, const int* in_sizes, int n_in,
                              void* d_out, int out_size) {
    const float* h = nullptr; const int* adj = nullptr; const float* W = nullptr; const float* a = nullptr;
    for (int k = 0; k < n_in; k++) {
        switch (in_sizes[k]) {
            case NROWS * INP:   h   = (const float*)d_in[k]; break;
            case NROWS * NROWS: adj = (const int*)d_in[k];   break;
            case INP * NOUT:    W   = (const float*)d_in[k]; break;
            case 2 * NOUT:      a   = (const float*)d_in[k]; break;
            default: break;
        }
    }
    float* out = (float*)d_out;

    cudaFuncSetAttribute(k4_hmma, cudaFuncAttributeMaxDynamicSharedMemorySize, DYNSMEM);

    kA     <<<128 + NROWS, 256>>>(h, W, a, adj);
    k4_hmma<<<128, 512, DYNSMEM>>>(out);
}

// round 7
// speedup vs baseline: 8.3468x; 1.4233x over previous
#include <cuda_runtime.h>
#include <cuda_fp16.h>
#include <stdint.h>

#define NROWS 8192
#define INP   512
#define NOUT  128
#define SLOPE 0.2f

// ---------------- device scratch ----------------
__device__ float  g_f1[NROWS];
__device__ float  g_f2[NROWS];
__device__ float  g_A[NROWS];
__device__ float  g_C[NROWS];
__device__ unsigned int g_bits[NROWS * 256];    // 8 MB bitpacked adj
__device__ uint4  g_UVT2[2 * 128 * 1024];       // 4 MB: {U,V} fp16 x 128 chunks x 16KB pre-swizzled B^T tiles
__device__ uint4  g_ZT[128 * 64];               // per chunk: 8 rows x 64 j fp16 (u, v, zero...)
__device__ float  g_pp[2 * NROWS * NOUT];       // pos-stream partials (per j-half)
__device__ float  g_pn[2 * NROWS * NOUT];       // neg-stream partials
__device__ float  g_zu[2 * NROWS];
__device__ float  g_zv[2 * NROWS];
__device__ unsigned int g_cnt;                  // ticket barrier (monotonic)

// ---------------- helpers ----------------
__device__ __forceinline__ uint32_t smem_u32(const void* p) {
    uint32_t r;
    asm("{ .reg .u64 t; cvta.to.shared.u64 t, %1; cvt.u32.u64 %0, t; }" : "=r"(r) : "l"(p));
    return r;
}
#define SW128(x) ((x) ^ (((x) >> 3) & 0x70))

#define LDSM_X4(r0, r1, r2, r3, addr) \
    asm volatile("ldmatrix.sync.aligned.m8n8.x4.shared.b16 {%0,%1,%2,%3}, [%4];" \
        : "=r"(r0), "=r"(r1), "=r"(r2), "=r"(r3) : "r"(addr))

#define MMA16816(d, a0, a1, a2, a3, b0, b1) \
    asm volatile("mma.sync.aligned.m16n8k16.row.col.f32.f16.f16.f32 " \
        "{%0,%1,%2,%3},{%4,%5,%6,%7},{%8,%9},{%0,%1,%2,%3};" \
        : "+f"((d)[0]), "+f"((d)[1]), "+f"((d)[2]), "+f"((d)[3]) \
        : "r"(a0), "r"(a1), "r"(a2), "r"(a3), "r"(b0), "r"(b1))

__device__ __forceinline__ void cp_async16(uint32_t dst, const void* src) {
    asm volatile("cp.async.cg.shared.global [%0], [%1], 16;" :: "r"(dst), "l"(src) : "memory");
}
#define CP_COMMIT() asm volatile("cp.async.commit_group;" ::: "memory")
#define CP_WAIT1()  asm volatile("cp.async.wait_group 1;" ::: "memory")

__device__ __forceinline__ unsigned pack_f16x2(float lo, float hi) {
    unsigned r;
    asm("cvt.rn.f16x2.f32 %0, %1, %2;" : "=r"(r) : "f"(hi), "f"(lo));
    return r;
}

// ============ kA: fused [bitpack adj] + [Wh GEMM + features + UVT/ZT production] ============
__global__ __launch_bounds__(256) void kA(const float* __restrict__ h, const float* __restrict__ W,
                                          const float* __restrict__ a, const int* __restrict__ adj) {
    if (blockIdx.x >= 128) {
        const int i = blockIdx.x - 128;
        const int w = threadIdx.x >> 5, lane = threadIdx.x & 31;
        const int* row = adj + (size_t)i * NROWS;
#pragma unroll
        for (int q = 0; q < 32; q++) {
            int widx = w + q * 8;
            int v = row[widx * 32 + lane];
            unsigned m = __ballot_sync(0xffffffffu, v != 0);
            if (lane == 0) g_bits[(size_t)i * 256 + widx] = m;
        }
        return;
    }

    __shared__ float hs[64][33];
    __shared__ float Ws[32][128];
    const int t  = threadIdx.x;
    const int i0 = blockIdx.x * 64;
    const int tx = t & 31;
    const int ty = t >> 5;

    float acc[8][4];
#pragma unroll
    for (int r = 0; r < 8; r++)
#pragma unroll
        for (int c = 0; c < 4; c++) acc[r][c] = 0.f;

    for (int k0 = 0; k0 < INP; k0 += 32) {
#pragma unroll
        for (int p = 0; p < 2; p++) {
            int u = t + p * 256;
            int r = u >> 3, kc = (u & 7) * 4;
            float4 hv = *(const float4*)(h + (size_t)(i0 + r) * INP + k0 + kc);
            hs[r][kc] = hv.x; hs[r][kc + 1] = hv.y; hs[r][kc + 2] = hv.z; hs[r][kc + 3] = hv.w;
        }
#pragma unroll
        for (int p = 0; p < 4; p++) {
            int u = t + p * 256;
            int kr = u >> 5, cc = (u & 31) * 4;
            *(float4*)&Ws[kr][cc] = *(const float4*)(W + (size_t)(k0 + kr) * NOUT + cc);
        }
        __syncthreads();
#pragma unroll
        for (int kk = 0; kk < 32; kk++) {
            float4 bv = *(float4*)&Ws[kk][tx * 4];
#pragma unroll
            for (int r = 0; r < 8; r++) {
                float av = hs[ty * 8 + r][kk];
                acc[r][0] += av * bv.x; acc[r][1] += av * bv.y;
                acc[r][2] += av * bv.z; acc[r][3] += av * bv.w;
            }
        }
        __syncthreads();
    }

    // ---- f1/f2 per row ----
    float4 a1 = __ldg((const float4*)(a + tx * 4));
    float4 a2 = __ldg((const float4*)(a + 128 + tx * 4));
    float uu[8], vv[8];
#pragma unroll
    for (int r = 0; r < 8; r++) {
        float s1 = acc[r][0] * a1.x + acc[r][1] * a1.y + acc[r][2] * a1.z + acc[r][3] * a1.w;
        float s2 = acc[r][0] * a2.x + acc[r][1] * a2.y + acc[r][2] * a2.z + acc[r][3] * a2.w;
#pragma unroll
        for (int off = 16; off > 0; off >>= 1) {
            s1 += __shfl_xor_sync(0xffffffffu, s1, off);
            s2 += __shfl_xor_sync(0xffffffffu, s2, off);
        }
        uu[r] = expf(s2);
        vv[r] = expf(SLOPE * s2);
        if (tx == r) {
            int j = i0 + ty * 8 + r;
            g_f1[j] = s1;
            g_f2[j] = s2;
            g_A[j]  = expf(s1);
            g_C[j]  = expf(SLOPE * s1);
        }
    }

    // ---- UVT writes (fp16): U and V matrices, pre-swizzled ----
    const int jbase = ty * 8;
    char* base = (char*)g_UVT2 + (size_t)blockIdx.x * 16384;
#pragma unroll
    for (int rp = 0; rp < 4; rp++) {
#pragma unroll
        for (int c = 0; c < 4; c++) {
            float U0 = uu[2 * rp] * acc[2 * rp][c],     U1 = uu[2 * rp + 1] * acc[2 * rp + 1][c];
            float V0 = vv[2 * rp] * acc[2 * rp][c],     V1 = vv[2 * rp + 1] * acc[2 * rp + 1][c];
            unsigned off = SW128((unsigned)((tx * 4 + c) * 128 + (jbase + 2 * rp) * 2));
            *(unsigned*)(base + off)            = pack_f16x2(U0, U1);
            *(unsigned*)(base + 2097152u + off) = pack_f16x2(V0, V1);
        }
    }

    // ---- ZT writes: row 0 = u, row 1 = v (fp16), rows 2..7 zero ----
    {
        char* zb = (char*)g_ZT + (size_t)blockIdx.x * 1024;
        int rsel = tx & 7;
        float us = uu[0], vs = vv[0];
#pragma unroll
        for (int r = 1; r < 8; r++) if (rsel == r) { us = uu[r]; vs = vv[r]; }
        int n = tx >> 3;  // 0..3
        if (n < 2) {
            float val = (n == 0) ? us : vs;
            unsigned off = (unsigned)(n * 128) + (((unsigned)((jbase + rsel) * 2)) ^ ((unsigned)n << 4));
            *(__half*)(zb + off) = __float2half(val);
        }
        if (t < 192) {
            int zn = 2 + (t >> 5);
            unsigned zoff = (unsigned)(zn * 128) + ((((unsigned)(t & 31)) * 4u) ^ ((unsigned)(zn & 7) << 4));
            *(unsigned*)(zb + zoff) = 0u;
        }
    }
}

// ============ K4: fp16 HMMA masked GEMMs + Z streams + device-wide combine ============
#define MASKBUF   32768                          // pos 16K + neg 16K
#define BTILE     16384
#define ZTB       1024
#define BBUF      (2 * BTILE + ZTB)              // 33792: U + V + z
#define DYNSMEM   (2 * MASKBUF + 2 * BBUF)       // 133120

__global__ void __launch_bounds__(512, 1) k4_hmma(float* __restrict__ out) {
    extern __shared__ __align__(16) char dyn[];
    __shared__ float s_f1[128];
    __shared__ float s_f2[4096];

    const int tid  = threadIdx.x;
    const int wid  = tid >> 5;
    const int lane = tid & 31;
    const int rt = blockIdx.x >> 1;
    const int hh = blockIdx.x & 1;
    const int i0 = rt << 7;
    const int j0 = hh << 12;

    const uint32_t dbase  = smem_u32(dyn);
    const uint32_t bbuf_u = dbase + 2u * MASKBUF;

    if (tid < 128) s_f1[tid] = g_f1[i0 + tid];
    for (int q = tid; q < 4096; q += 512) s_f2[q] = g_f2[j0 + q];
    __syncthreads();

    float dp[2][4][4], dn[2][4][4];
    float dzp[2][4], dzn[2][4];
#pragma unroll
    for (int mt = 0; mt < 2; mt++) {
#pragma unroll
        for (int nt = 0; nt < 4; nt++)
#pragma unroll
            for (int r = 0; r < 4; r++) { dp[mt][nt][r] = 0.f; dn[mt][nt][r] = 0.f; }
#pragma unroll
        for (int r = 0; r < 4; r++) { dzp[mt][r] = 0.f; dzn[mt][r] = 0.f; }
    }

    const int warp_m = wid >> 2;
    const int warp_n = wid & 3;
    const bool diag = (warp_m == warp_n);
    const int ib = warp_m << 5;
    const int cb = warp_n << 5;

    const int ri0 = ib + (lane & 15);
    const int ri1 = ri0 + 16;
    const uint32_t arow0 = (uint32_t)ri0 * 128u, asw0 = (uint32_t)(ri0 & 7) << 4;
    const uint32_t arow1 = (uint32_t)ri1 * 128u, asw1 = (uint32_t)(ri1 & 7) << 4;
    const uint32_t akh   = (uint32_t)(lane >> 4) << 4;
    const int cr = cb + lane;
    const uint32_t brow = (uint32_t)cr * 128u, bsw = (uint32_t)(cr & 7) << 4;

    const uint32_t zn   = (uint32_t)(lane >> 2);
    const uint32_t zsw  = (zn & 7u) << 4;
    const uint32_t zrow = 2u * BTILE + zn * 128u;
    const uint32_t zkb  = ((uint32_t)(lane & 3)) << 2;

    // ---- mask tile builder (chunk c -> buffer mb) ----
    auto build_masks = [&](int c, int mb) {
        char* mdst = dyn + mb * MASKBUF;
        const int tch = c << 6;
#pragma unroll
        for (int un = 0; un < 2; un++) {
            const int unit = (tid << 1) | un;
            const int i  = unit >> 3;
            const int jl = (unit & 7) << 3;
            const unsigned wrd = g_bits[(size_t)(i0 + i) * 256 + (unsigned)((j0 + tch + jl) >> 5)];
            const unsigned bits8 = (wrd >> (jl & 31)) & 0xFFu;
            const float thr = -s_f1[i];
            const uint32_t rbase = (uint32_t)i * 128u;
            const uint32_t rsw   = (uint32_t)(i & 7) << 4;
#pragma unroll
            for (int p = 0; p < 4; p++) {
                const int jj = jl + (p << 1);
                const float fa = s_f2[tch + jj];
                const float fb = s_f2[tch + jj + 1];
                const unsigned b0 = (bits8 >> (p << 1)) & 1u;
                const unsigned b1 = (bits8 >> ((p << 1) + 1)) & 1u;
                const unsigned q0 = (fa >= thr) ? 1u : 0u;
                const unsigned q1 = (fb >= thr) ? 1u : 0u;
                const unsigned wp = ((b0 & q0)        ? 0x3C00u : 0u) | ((b1 & q1)        ? 0x3C000000u : 0u);
                const unsigned wn = ((b0 & (q0 ^ 1u)) ? 0x3C00u : 0u) | ((b1 & (q1 ^ 1u)) ? 0x3C000000u : 0u);
                const uint32_t off = rbase + (((uint32_t)(jj << 1)) ^ rsw);
                *(unsigned*)(mdst + off)          = wp;
                *(unsigned*)(mdst + 16384 + off)  = wn;
            }
        }
    };

    // ---- B prefetch (chunk c -> buffer bb): 32KB UV + 1KB z ----
    auto prefetch_B = [&](int c, int bb) {
        const int nc = (hh << 6) + c;
        const uint32_t dstb = bbuf_u + (uint32_t)bb * BBUF;
        const char* srcb = (const char*)g_UVT2 + (size_t)nc * 16384;
#pragma unroll
        for (int pass = 0; pass < 4; pass++) {
            int u = tid + pass * 512;
            int m = u >> 10;
            uint32_t off = (uint32_t)(u & 1023) << 4;
            cp_async16(dstb + (uint32_t)m * BTILE + off, srcb + (size_t)m * 2097152 + off);
        }
        if (tid < 64)
            cp_async16(dstb + 2u * BTILE + (uint32_t)tid * 16u,
                       (const char*)g_ZT + (size_t)nc * 1024 + tid * 16);
    };

    // ---- prologue: B0, B1 in flight; masks for chunk 0 built ----
    prefetch_B(0, 0); CP_COMMIT();
    prefetch_B(1, 1); CP_COMMIT();
    build_masks(0, 0);

    for (int t = 0; t < 64; t++) {
        CP_WAIT1();          // B[t] resident (only B[t+1] may be pending)
        __syncthreads();     // masks[t] (built last iter) + B[t] visible

        const uint32_t mpos = dbase + (uint32_t)(t & 1) * MASKBUF;
        const uint32_t mneg = mpos + 16384u;
        const uint32_t bufb = bbuf_u + (uint32_t)(t & 1) * BBUF;

#pragma unroll
        for (int ks = 0; ks < 4; ks++) {
            const uint32_t joff = ((uint32_t)ks << 5) | akh;
            uint32_t ap0[4], ap1[4], an0[4], an1[4];
            LDSM_X4(ap0[0], ap0[1], ap0[2], ap0[3], mpos + arow0 + (joff ^ asw0));
            LDSM_X4(ap1[0], ap1[1], ap1[2], ap1[3], mpos + arow1 + (joff ^ asw1));
            LDSM_X4(an0[0], an0[1], an0[2], an0[3], mneg + arow0 + (joff ^ asw0));
            LDSM_X4(an1[0], an1[1], an1[2], an1[3], mneg + arow1 + (joff ^ asw1));

            // U part -> dp
            {
                uint32_t b0[4], b1[4];
                const uint32_t pb = bufb + brow;
                LDSM_X4(b0[0], b0[1], b0[2], b0[3], pb + ((((uint32_t)ks << 5) | 0u)  ^ bsw));
                LDSM_X4(b1[0], b1[1], b1[2], b1[3], pb + ((((uint32_t)ks << 5) | 16u) ^ bsw));
#pragma unroll
                for (int nt = 0; nt < 4; nt++) {
                    MMA16816(dp[0][nt], ap0[0], ap0[1], ap0[2], ap0[3], b0[nt], b1[nt]);
                    MMA16816(dp[1][nt], ap1[0], ap1[1], ap1[2], ap1[3], b0[nt], b1[nt]);
                }
            }
            // V part -> dn
            {
                uint32_t b0[4], b1[4];
                const uint32_t pb = bufb + BTILE + brow;
                LDSM_X4(b0[0], b0[1], b0[2], b0[3], pb + ((((uint32_t)ks << 5) | 0u)  ^ bsw));
                LDSM_X4(b1[0], b1[1], b1[2], b1[3], pb + ((((uint32_t)ks << 5) | 16u) ^ bsw));
#pragma unroll
                for (int nt = 0; nt < 4; nt++) {
                    MMA16816(dn[0][nt], an0[0], an0[1], an0[2], an0[3], b0[nt], b1[nt]);
                    MMA16816(dn[1][nt], an1[0], an1[1], an1[2], an1[3], b0[nt], b1[nt]);
                }
            }
            // Z streams (diag warps)
            if (diag) {
                const uint32_t zk = ((uint32_t)ks << 5) + zkb;
                const uint32_t a0 = bufb + zrow + (zk ^ zsw);
                const uint32_t a1 = bufb + zrow + ((zk + 16u) ^ zsw);
                uint32_t bz0, bz1;
                asm volatile("ld.shared.b32 %0, [%1];" : "=r"(bz0) : "r"(a0));
                asm volatile("ld.shared.b32 %0, [%1];" : "=r"(bz1) : "r"(a1));
                MMA16816(dzp[0], ap0[0], ap0[1], ap0[2], ap0[3], bz0, bz1);
                MMA16816(dzp[1], ap1[0], ap1[1], ap1[2], ap1[3], bz0, bz1);
                MMA16816(dzn[0], an0[0], an0[1], an0[2], an0[3], bz0, bz1);
                MMA16816(dzn[1], an1[0], an1[1], an1[2], an1[3], bz0, bz1);
            }
        }

        // build next chunk's masks into the other buffer (overlaps other warps' MMA tail)
        if (t < 63) build_masks(t + 1, (t + 1) & 1);
        // prefetch B[t+2]
        if (t < 62) prefetch_B(t + 2, t & 1);
        CP_COMMIT();
    }

    // ---- write raw partials ----
    float* pdst = g_pp + (size_t)hh * (NROWS * NOUT);
    float* ndst = g_pn + (size_t)hh * (NROWS * NOUT);
#pragma unroll
    for (int mt = 0; mt < 2; mt++) {
        const int r0 = i0 + ib + mt * 16 + (lane >> 2);
        const int r1 = r0 + 8;
#pragma unroll
        for (int nt = 0; nt < 4; nt++) {
            const int c = cb + nt * 8 + ((lane & 3) << 1);
            *(float2*)&pdst[(size_t)r0 * NOUT + c] = make_float2(dp[mt][nt][0], dp[mt][nt][1]);
            *(float2*)&pdst[(size_t)r1 * NOUT + c] = make_float2(dp[mt][nt][2], dp[mt][nt][3]);
            *(float2*)&ndst[(size_t)r0 * NOUT + c] = make_float2(dn[mt][nt][0], dn[mt][nt][1]);
            *(float2*)&ndst[(size_t)r1 * NOUT + c] = make_float2(dn[mt][nt][2], dn[mt][nt][3]);
        }
    }
    if (diag) {
#pragma unroll
        for (int mt = 0; mt < 2; mt++) {
            const int r0 = i0 + ib + mt * 16 + (lane >> 2);
            if ((lane & 3) == 0) {        // this lane owns cols 0,1 (regs 0/1 rows r0; 2/3 rows r0+8)
                g_zu[hh * NROWS + r0]     = dzp[mt][0];
                g_zu[hh * NROWS + r0 + 8] = dzp[mt][2];
                g_zv[hh * NROWS + r0]     = dzn[mt][1];
                g_zv[hh * NROWS + r0 + 8] = dzn[mt][3];
            }
        }
    }

    // ---- device-wide barrier (grid=128, 1 CTA/SM: all resident) ----
    __threadfence();
    __syncthreads();
    if (tid == 0) {
        unsigned t0 = atomicAdd(&g_cnt, 1u);
        unsigned target = ((t0 >> 7) + 1u) << 7;
        unsigned cur;
        do {
            asm volatile("ld.acquire.gpu.u32 %0, [%1];" : "=r"(cur) : "l"(&g_cnt));
            if (cur < target) __nanosleep(128);
        } while (cur < target);
    }
    __syncthreads();

    // ---- combine: normalize rows [bid*64, bid*64+64) ----
    {
        const int rbase = blockIdx.x * 64;
#pragma unroll
        for (int it = 0; it < 4; it++) {
            int u = tid + it * 512;
            int r = rbase + (u >> 5);
            int c = (u & 31) * 4;
            float A = g_A[r], Cc = g_C[r];
            float z = A * (g_zu[r] + g_zu[NROWS + r]) + Cc * (g_zv[r] + g_zv[NROWS + r]);
            float zi = 1.f / z;
            const float4 p0 = *(const float4*)&g_pp[(size_t)r * NOUT + c];
            const float4 p1 = *(const float4*)&g_pp[(size_t)(NROWS + r) * NOUT + c];
            const float4 n0 = *(const float4*)&g_pn[(size_t)r * NOUT + c];
            const float4 n1 = *(const float4*)&g_pn[(size_t)(NROWS + r) * NOUT + c];
            float4 o;
            o.x = (A * (p0.x + p1.x) + Cc * (n0.x + n1.x)) * zi;
            o.y = (A * (p0.y + p1.y) + Cc * (n0.y + n1.y)) * zi;
            o.z = (A * (p0.z + p1.z) + Cc * (n0.z + n1.z)) * zi;
            o.w = (A * (p0.w + p1.w) + Cc * (n0.w + n1.w)) * zi;
            *(float4*)&out[(size_t)r * NOUT + c] = o;
        }
    }
}

// ---------------- launcher ----------------
extern "C" void kernel_launch(void* const* d_in, const int* in_sizes, int n_in,
                              void* d_out, int out_size) {
    const float* h = nullptr; const int* adj = nullptr; const float* W = nullptr; const float* a = nullptr;
    for (int k = 0; k < n_in; k++) {
        switch (in_sizes[k]) {
            case NROWS * INP:   h   = (const float*)d_in[k]; break;
            case NROWS * NROWS: adj = (const int*)d_in[k];   break;
            case INP * NOUT:    W   = (const float*)d_in[k]; break;
            case 2 * NOUT:      a   = (const float*)d_in[k]; break;
            default: break;
        }
    }
    float* out = (float*)d_out;

    cudaFuncSetAttribute(k4_hmma, cudaFuncAttributeMaxDynamicSharedMemorySize, DYNSMEM);

    kA     <<<128 + NROWS, 256>>>(h, W, a, adj);
    k4_hmma<<<128, 512, DYNSMEM>>>(out);
}

// round 8
// speedup vs baseline: 9.3215x; 1.1168x over previous
#include <cuda_runtime.h>
#include <cuda_fp16.h>
#include <stdint.h>

#define NROWS 8192
#define INP   512
#define NOUT  128
#define SLOPE 0.2f

// ---------------- device scratch ----------------
__device__ float  g_f1[NROWS];
__device__ float  g_f2[NROWS];
__device__ float  g_A[NROWS];
__device__ float  g_C[NROWS];
__device__ unsigned int g_bits[NROWS * 256];    // 8 MB bitpacked adj
__device__ uint4  g_UVT2[2 * 128 * 1024];       // 4 MB: {U,V} fp16 x 128 chunks x 16KB pre-swizzled B^T tiles
__device__ uint4  g_ZT[128 * 64];               // per chunk: 8 rows x 64 j fp16 (u, v, zero...)
__device__ float  g_pp[2 * NROWS * NOUT];
__device__ float  g_pn[2 * NROWS * NOUT];
__device__ float  g_zu[2 * NROWS];
__device__ float  g_zv[2 * NROWS];
__device__ unsigned int g_cnt;

// ---------------- helpers ----------------
__device__ __forceinline__ uint32_t smem_u32(const void* p) {
    uint32_t r;
    asm("{ .reg .u64 t; cvta.to.shared.u64 t, %1; cvt.u32.u64 %0, t; }" : "=r"(r) : "l"(p));
    return r;
}
#define SW128(x) ((x) ^ (((x) >> 3) & 0x70))

#define LDSM_X4(r0, r1, r2, r3, addr) \
    asm volatile("ldmatrix.sync.aligned.m8n8.x4.shared.b16 {%0,%1,%2,%3}, [%4];" \
        : "=r"(r0), "=r"(r1), "=r"(r2), "=r"(r3) : "r"(addr))

#define MMA16816(d, a0, a1, a2, a3, b0, b1) \
    asm volatile("mma.sync.aligned.m16n8k16.row.col.f32.f16.f16.f32 " \
        "{%0,%1,%2,%3},{%4,%5,%6,%7},{%8,%9},{%0,%1,%2,%3};" \
        : "+f"((d)[0]), "+f"((d)[1]), "+f"((d)[2]), "+f"((d)[3]) \
        : "r"(a0), "r"(a1), "r"(a2), "r"(a3), "r"(b0), "r"(b1))

__device__ __forceinline__ void cp_async16(uint32_t dst, const void* src) {
    asm volatile("cp.async.cg.shared.global [%0], [%1], 16;" :: "r"(dst), "l"(src) : "memory");
}
__device__ __forceinline__ void cp_async8(uint32_t dst, const void* src) {
    asm volatile("cp.async.ca.shared.global [%0], [%1], 8;" :: "r"(dst), "l"(src) : "memory");
}
#define CP_COMMIT() asm volatile("cp.async.commit_group;" ::: "memory")
#define CP_WAIT1()  asm volatile("cp.async.wait_group 1;" ::: "memory")

__device__ __forceinline__ unsigned pack_f16x2(float lo, float hi) {
    unsigned r;
    asm("cvt.rn.f16x2.f32 %0, %1, %2;" : "=r"(r) : "f"(hi), "f"(lo));
    return r;
}
__device__ __forceinline__ unsigned prmt(unsigned a, unsigned b, unsigned s) {
    unsigned r;
    asm("prmt.b32 %0, %1, %2, %3;" : "=r"(r) : "r"(a), "r"(b), "r"(s));
    return r;
}

// ============ kA: fused [bitpack adj] + [Wh GEMM + features + UVT/ZT production] ============
__global__ __launch_bounds__(256) void kA(const float* __restrict__ h, const float* __restrict__ W,
                                          const float* __restrict__ a, const int* __restrict__ adj) {
    if (blockIdx.x >= 128) {
        const int i = blockIdx.x - 128;
        const int t = threadIdx.x;
        const int l = t & 31;
        const int4* row = (const int4*)(adj + (size_t)i * NROWS);
        int4 v[8];
#pragma unroll
        for (int k = 0; k < 8; k++) v[k] = row[k * 256 + t];   // MLP 8
#pragma unroll
        for (int k = 0; k < 8; k++) {
            unsigned nib = (v[k].x != 0 ? 1u : 0u) | (v[k].y != 0 ? 2u : 0u)
                         | (v[k].z != 0 ? 4u : 0u) | (v[k].w != 0 ? 8u : 0u);
            unsigned m = nib << ((t & 7) * 4);
            m |= __shfl_xor_sync(0xffffffffu, m, 1);
            m |= __shfl_xor_sync(0xffffffffu, m, 2);
            m |= __shfl_xor_sync(0xffffffffu, m, 4);
            if ((l & 7) == 0) g_bits[(size_t)i * 256 + k * 32 + (t >> 3)] = m;
        }
        return;
    }

    __shared__ float hs[64][33];
    __shared__ float Ws[32][128];
    const int t  = threadIdx.x;
    const int i0 = blockIdx.x * 64;
    const int tx = t & 31;
    const int ty = t >> 5;

    float acc[8][4];
#pragma unroll
    for (int r = 0; r < 8; r++)
#pragma unroll
        for (int c = 0; c < 4; c++) acc[r][c] = 0.f;

    for (int k0 = 0; k0 < INP; k0 += 32) {
#pragma unroll
        for (int p = 0; p < 2; p++) {
            int u = t + p * 256;
            int r = u >> 3, kc = (u & 7) * 4;
            float4 hv = *(const float4*)(h + (size_t)(i0 + r) * INP + k0 + kc);
            hs[r][kc] = hv.x; hs[r][kc + 1] = hv.y; hs[r][kc + 2] = hv.z; hs[r][kc + 3] = hv.w;
        }
#pragma unroll
        for (int p = 0; p < 4; p++) {
            int u = t + p * 256;
            int kr = u >> 5, cc = (u & 31) * 4;
            *(float4*)&Ws[kr][cc] = *(const float4*)(W + (size_t)(k0 + kr) * NOUT + cc);
        }
        __syncthreads();
#pragma unroll
        for (int kk = 0; kk < 32; kk++) {
            float4 bv = *(float4*)&Ws[kk][tx * 4];
#pragma unroll
            for (int r = 0; r < 8; r++) {
                float av = hs[ty * 8 + r][kk];
                acc[r][0] += av * bv.x; acc[r][1] += av * bv.y;
                acc[r][2] += av * bv.z; acc[r][3] += av * bv.w;
            }
        }
        __syncthreads();
    }

    float4 a1 = __ldg((const float4*)(a + tx * 4));
    float4 a2 = __ldg((const float4*)(a + 128 + tx * 4));
    float uu[8], vv[8];
#pragma unroll
    for (int r = 0; r < 8; r++) {
        float s1 = acc[r][0] * a1.x + acc[r][1] * a1.y + acc[r][2] * a1.z + acc[r][3] * a1.w;
        float s2 = acc[r][0] * a2.x + acc[r][1] * a2.y + acc[r][2] * a2.z + acc[r][3] * a2.w;
#pragma unroll
        for (int off = 16; off > 0; off >>= 1) {
            s1 += __shfl_xor_sync(0xffffffffu, s1, off);
            s2 += __shfl_xor_sync(0xffffffffu, s2, off);
        }
        uu[r] = expf(s2);
        vv[r] = expf(SLOPE * s2);
        if (tx == r) {
            int j = i0 + ty * 8 + r;
            g_f1[j] = s1;
            g_f2[j] = s2;
            g_A[j]  = expf(s1);
            g_C[j]  = expf(SLOPE * s1);
        }
    }

    const int jbase = ty * 8;
    char* base = (char*)g_UVT2 + (size_t)blockIdx.x * 16384;
#pragma unroll
    for (int rp = 0; rp < 4; rp++) {
#pragma unroll
        for (int c = 0; c < 4; c++) {
            float U0 = uu[2 * rp] * acc[2 * rp][c],     U1 = uu[2 * rp + 1] * acc[2 * rp + 1][c];
            float V0 = vv[2 * rp] * acc[2 * rp][c],     V1 = vv[2 * rp + 1] * acc[2 * rp + 1][c];
            unsigned off = SW128((unsigned)((tx * 4 + c) * 128 + (jbase + 2 * rp) * 2));
            *(unsigned*)(base + off)            = pack_f16x2(U0, U1);
            *(unsigned*)(base + 2097152u + off) = pack_f16x2(V0, V1);
        }
    }

    {
        char* zb = (char*)g_ZT + (size_t)blockIdx.x * 1024;
        int rsel = tx & 7;
        float us = uu[0], vs = vv[0];
#pragma unroll
        for (int r = 1; r < 8; r++) if (rsel == r) { us = uu[r]; vs = vv[r]; }
        int n = tx >> 3;
        if (n < 2) {
            float val = (n == 0) ? us : vs;
            unsigned off = (unsigned)(n * 128) + (((unsigned)((jbase + rsel) * 2)) ^ ((unsigned)n << 4));
            *(__half*)(zb + off) = __float2half(val);
        }
        if (t < 192) {
            int zn = 2 + (t >> 5);
            unsigned zoff = (unsigned)(zn * 128) + ((((unsigned)(t & 31)) * 4u) ^ ((unsigned)(zn & 7) << 4));
            *(unsigned*)(zb + zoff) = 0u;
        }
    }
}

// ============ K4: fp16 HMMA masked GEMMs + Z streams + device-wide combine ============
#define MASKBUF   32768
#define BTILE     16384
#define ZTB       1024
#define BBUF      (2 * BTILE + ZTB)              // 33792
#define DYNSMEM   (2 * MASKBUF + 2 * BBUF)       // 133120

__global__ void __launch_bounds__(512, 1) k4_hmma(float* __restrict__ out) {
    extern __shared__ __align__(16) char dyn[];
    __shared__ float s_f1[128];
    __shared__ __align__(16) float s_f2[4096];
    __shared__ __align__(16) unsigned sbits[3 * 256];   // 3 slots x (128 rows x 2 words)

    const int tid  = threadIdx.x;
    const int wid  = tid >> 5;
    const int lane = tid & 31;
    const int rt = blockIdx.x >> 1;
    const int hh = blockIdx.x & 1;
    const int i0 = rt << 7;
    const int j0 = hh << 12;

    const uint32_t dbase  = smem_u32(dyn);
    const uint32_t bbuf_u = dbase + 2u * MASKBUF;
    const uint32_t sbits_u = smem_u32(sbits);

    if (tid < 128) s_f1[tid] = g_f1[i0 + tid];
    for (int q = tid; q < 4096; q += 512) s_f2[q] = g_f2[j0 + q];
    __syncthreads();

    float dp[2][4][4], dn[2][4][4];
    float dzp[2][4], dzn[2][4];
#pragma unroll
    for (int mt = 0; mt < 2; mt++) {
#pragma unroll
        for (int nt = 0; nt < 4; nt++)
#pragma unroll
            for (int r = 0; r < 4; r++) { dp[mt][nt][r] = 0.f; dn[mt][nt][r] = 0.f; }
#pragma unroll
        for (int r = 0; r < 4; r++) { dzp[mt][r] = 0.f; dzn[mt][r] = 0.f; }
    }

    const int warp_m = wid >> 2;
    const int warp_n = wid & 3;
    const bool diag = (warp_m == warp_n);
    const int ib = warp_m << 5;
    const int cb = warp_n << 5;

    const int ri0 = ib + (lane & 15);
    const int ri1 = ri0 + 16;
    const uint32_t arow0 = (uint32_t)ri0 * 128u, asw0 = (uint32_t)(ri0 & 7) << 4;
    const uint32_t arow1 = (uint32_t)ri1 * 128u, asw1 = (uint32_t)(ri1 & 7) << 4;
    const uint32_t akh   = (uint32_t)(lane >> 4) << 4;
    const int cr = cb + lane;
    const uint32_t brow = (uint32_t)cr * 128u, bsw = (uint32_t)(cr & 7) << 4;

    const uint32_t zn   = (uint32_t)(lane >> 2);
    const uint32_t zsw  = (zn & 7u) << 4;
    const uint32_t zrow = 2u * BTILE + zn * 128u;
    const uint32_t zkb  = ((uint32_t)(lane & 3)) << 2;

    // ---- bits prefetch: chunk c -> slot c%3 (128 rows x 8B) ----
    auto prefetch_bits = [&](int c) {
        if (tid < 128) {
            uint32_t dst = sbits_u + (uint32_t)(c % 3) * 1024u + (uint32_t)tid * 8u;
            const unsigned* src = &g_bits[(size_t)(i0 + tid) * 256 + (unsigned)((j0 + (c << 6)) >> 5)];
            cp_async8(dst, src);
        }
    };

    // ---- mask tile builder (chunk c -> buffer mb); bits from SMEM slot c%3 ----
    auto build_masks = [&](int c, int mb) {
        char* mdst = dyn + mb * MASKBUF;
        const int tch = c << 6;
        const unsigned* sb = sbits + (c % 3) * 256;
#pragma unroll
        for (int un = 0; un < 2; un++) {
            const int unit = (tid << 1) | un;
            const int i  = unit >> 3;
            const int jl = (unit & 7) << 3;
            const unsigned word = sb[i * 2 + (jl >> 5)];
            const unsigned bits8 = (word >> (jl & 31)) & 0xFFu;
            const float thr = -s_f1[i];
            const float4 fA = *(const float4*)&s_f2[tch + jl];
            const float4 fB = *(const float4*)&s_f2[tch + jl + 4];
            const float fs[8] = {fA.x, fA.y, fA.z, fA.w, fB.x, fB.y, fB.z, fB.w};
            unsigned pn[8];
#pragma unroll
            for (int e = 0; e < 8; e++) {
                unsigned sel = (fs[e] >= thr) ? 0x00003C00u : 0x3C000000u;
                pn[e] = ((bits8 >> e) & 1u) * sel;
            }
            uint4 wp4, wn4;
            wp4.x = prmt(pn[0], pn[1], 0x5410u); wn4.x = prmt(pn[0], pn[1], 0x7632u);
            wp4.y = prmt(pn[2], pn[3], 0x5410u); wn4.y = prmt(pn[2], pn[3], 0x7632u);
            wp4.z = prmt(pn[4], pn[5], 0x5410u); wn4.z = prmt(pn[4], pn[5], 0x7632u);
            wp4.w = prmt(pn[6], pn[7], 0x5410u); wn4.w = prmt(pn[6], pn[7], 0x7632u);
            const uint32_t off = (uint32_t)i * 128u + (((uint32_t)(jl << 1)) ^ ((uint32_t)(i & 7) << 4));
            *(uint4*)(mdst + off)          = wp4;
            *(uint4*)(mdst + 16384 + off)  = wn4;
        }
    };

    // ---- B prefetch (chunk c -> buffer bb): 32KB UV + 1KB z ----
    auto prefetch_B = [&](int c, int bb) {
        const int nc = (hh << 6) + c;
        const uint32_t dstb = bbuf_u + (uint32_t)bb * BBUF;
        const char* srcb = (const char*)g_UVT2 + (size_t)nc * 16384;
#pragma unroll
        for (int pass = 0; pass < 4; pass++) {
            int u = tid + pass * 512;
            int m = u >> 10;
            uint32_t off = (uint32_t)(u & 1023) << 4;
            cp_async16(dstb + (uint32_t)m * BTILE + off, srcb + (size_t)m * 2097152 + off);
        }
        if (tid < 64)
            cp_async16(dstb + 2u * BTILE + (uint32_t)tid * 16u,
                       (const char*)g_ZT + (size_t)nc * 1024 + tid * 16);
    };

    // ---- prologue ----
    prefetch_bits(0);
    prefetch_bits(1);
    prefetch_B(0, 0);
    CP_COMMIT();                 // group 0: B0, z0, bits0, bits1
    prefetch_bits(2);
    prefetch_B(1, 1);
    CP_COMMIT();                 // group 1: B1, z1, bits2
    CP_WAIT1();                  // group 0 complete
    __syncthreads();
    build_masks(0, 0);

    for (int t = 0; t < 64; t++) {
        CP_WAIT1();              // group t complete (B[t], bits[t+1])
        __syncthreads();         // masks[t] visible

        const uint32_t mpos = dbase + (uint32_t)(t & 1) * MASKBUF;
        const uint32_t mneg = mpos + 16384u;
        const uint32_t bufb = bbuf_u + (uint32_t)(t & 1) * BBUF;

#pragma unroll
        for (int ks = 0; ks < 4; ks++) {
            const uint32_t joff = ((uint32_t)ks << 5) | akh;
            uint32_t ap0[4], ap1[4], an0[4], an1[4];
            LDSM_X4(ap0[0], ap0[1], ap0[2], ap0[3], mpos + arow0 + (joff ^ asw0));
            LDSM_X4(ap1[0], ap1[1], ap1[2], ap1[3], mpos + arow1 + (joff ^ asw1));
            LDSM_X4(an0[0], an0[1], an0[2], an0[3], mneg + arow0 + (joff ^ asw0));
            LDSM_X4(an1[0], an1[1], an1[2], an1[3], mneg + arow1 + (joff ^ asw1));

            {
                uint32_t b0[4], b1[4];
                const uint32_t pb = bufb + brow;
                LDSM_X4(b0[0], b0[1], b0[2], b0[3], pb + ((((uint32_t)ks << 5) | 0u)  ^ bsw));
                LDSM_X4(b1[0], b1[1], b1[2], b1[3], pb + ((((uint32_t)ks << 5) | 16u) ^ bsw));
#pragma unroll
                for (int nt = 0; nt < 4; nt++) {
                    MMA16816(dp[0][nt], ap0[0], ap0[1], ap0[2], ap0[3], b0[nt], b1[nt]);
                    MMA16816(dp[1][nt], ap1[0], ap1[1], ap1[2], ap1[3], b0[nt], b1[nt]);
                }
            }
            {
                uint32_t b0[4], b1[4];
                const uint32_t pb = bufb + BTILE + brow;
                LDSM_X4(b0[0], b0[1], b0[2], b0[3], pb + ((((uint32_t)ks << 5) | 0u)  ^ bsw));
                LDSM_X4(b1[0], b1[1], b1[2], b1[3], pb + ((((uint32_t)ks << 5) | 16u) ^ bsw));
#pragma unroll
                for (int nt = 0; nt < 4; nt++) {
                    MMA16816(dn[0][nt], an0[0], an0[1], an0[2], an0[3], b0[nt], b1[nt]);
                    MMA16816(dn[1][nt], an1[0], an1[1], an1[2], an1[3], b0[nt], b1[nt]);
                }
            }
            if (diag) {
                const uint32_t zk = ((uint32_t)ks << 5) + zkb;
                const uint32_t a0 = bufb + zrow + (zk ^ zsw);
                const uint32_t a1 = bufb + zrow + ((zk + 16u) ^ zsw);
                uint32_t bz0, bz1;
                asm volatile("ld.shared.b32 %0, [%1];" : "=r"(bz0) : "r"(a0));
                asm volatile("ld.shared.b32 %0, [%1];" : "=r"(bz1) : "r"(a1));
                MMA16816(dzp[0], ap0[0], ap0[1], ap0[2], ap0[3], bz0, bz1);
                MMA16816(dzp[1], ap1[0], ap1[1], ap1[2], ap1[3], bz0, bz1);
                MMA16816(dzn[0], an0[0], an0[1], an0[2], an0[3], bz0, bz1);
                MMA16816(dzn[1], an1[0], an1[1], an1[2], an1[3], bz0, bz1);
            }
        }

        if (t < 63) build_masks(t + 1, (t + 1) & 1);
        if (t < 62) {
            prefetch_B(t + 2, t & 1);
            if (t + 3 < 64) prefetch_bits(t + 3);
        }
        CP_COMMIT();
    }

    // ---- write raw partials ----
    float* pdst = g_pp + (size_t)hh * (NROWS * NOUT);
    float* ndst = g_pn + (size_t)hh * (NROWS * NOUT);
#pragma unroll
    for (int mt = 0; mt < 2; mt++) {
        const int r0 = i0 + ib + mt * 16 + (lane >> 2);
        const int r1 = r0 + 8;
#pragma unroll
        for (int nt = 0; nt < 4; nt++) {
            const int c = cb + nt * 8 + ((lane & 3) << 1);
            *(float2*)&pdst[(size_t)r0 * NOUT + c] = make_float2(dp[mt][nt][0], dp[mt][nt][1]);
            *(float2*)&pdst[(size_t)r1 * NOUT + c] = make_float2(dp[mt][nt][2], dp[mt][nt][3]);
            *(float2*)&ndst[(size_t)r0 * NOUT + c] = make_float2(dn[mt][nt][0], dn[mt][nt][1]);
            *(float2*)&ndst[(size_t)r1 * NOUT + c] = make_float2(dn[mt][nt][2], dn[mt][nt][3]);
        }
    }
    if (diag) {
#pragma unroll
        for (int mt = 0; mt < 2; mt++) {
            const int r0 = i0 + ib + mt * 16 + (lane >> 2);
            if ((lane & 3) == 0) {
                g_zu[hh * NROWS + r0]     = dzp[mt][0];
                g_zu[hh * NROWS + r0 + 8] = dzp[mt][2];
                g_zv[hh * NROWS + r0]     = dzn[mt][1];
                g_zv[hh * NROWS + r0 + 8] = dzn[mt][3];
            }
        }
    }

    // ---- device-wide barrier ----
    __threadfence();
    __syncthreads();
    if (tid == 0) {
        unsigned t0 = atomicAdd(&g_cnt, 1u);
        unsigned target = ((t0 >> 7) + 1u) << 7;
        unsigned cur;
        do {
            asm volatile("ld.acquire.gpu.u32 %0, [%1];" : "=r"(cur) : "l"(&g_cnt));
            if (cur < target) __nanosleep(128);
        } while (cur < target);
    }
    __syncthreads();

    // ---- combine ----
    {
        const int rbase = blockIdx.x * 64;
#pragma unroll
        for (int it = 0; it < 4; it++) {
            int u = tid + it * 512;
            int r = rbase + (u >> 5);
            int c = (u & 31) * 4;
            float A = g_A[r], Cc = g_C[r];
            float z = A * (g_zu[r] + g_zu[NROWS + r]) + Cc * (g_zv[r] + g_zv[NROWS + r]);
            float zi = 1.f / z;
            const float4 p0 = *(const float4*)&g_pp[(size_t)r * NOUT + c];
            const float4 p1 = *(const float4*)&g_pp[(size_t)(NROWS + r) * NOUT + c];
            const float4 n0 = *(const float4*)&g_pn[(size_t)r * NOUT + c];
            const float4 n1 = *(const float4*)&g_pn[(size_t)(NROWS + r) * NOUT + c];
            float4 o;
            o.x = (A * (p0.x + p1.x) + Cc * (n0.x + n1.x)) * zi;
            o.y = (A * (p0.y + p1.y) + Cc * (n0.y + n1.y)) * zi;
            o.z = (A * (p0.z + p1.z) + Cc * (n0.z + n1.z)) * zi;
            o.w = (A * (p0.w + p1.w) + Cc * (n0.w + n1.w)) * zi;
            *(float4*)&out[(size_t)r * NOUT + c] = o;
        }
    }
}

// ---------------- launcher ----------------
extern "C" void kernel_launch(void* const* d_in, const int* in_sizes, int n_in,
                              void* d_out, int out_size) {
    const float* h = nullptr; const int* adj = nullptr; const float* W = nullptr; const float* a = nullptr;
    for (int k = 0; k < n_in; k++) {
        switch (in_sizes[k]) {
            case NROWS * INP:   h   = (const float*)d_in[k]; break;
            case NROWS * NROWS: adj = (const int*)d_in[k];   break;
            case INP * NOUT:    W   = (const float*)d_in[k]; break;
            case 2 * NOUT:      a   = (const float*)d_in[k]; break;
            default: break;
        }
    }
    float* out = (float*)d_out;

    cudaFuncSetAttribute(k4_hmma, cudaFuncAttributeMaxDynamicSharedMemorySize, DYNSMEM);

    kA     <<<128 + NROWS, 256>>>(h, W, a, adj);
    k4_hmma<<<128, 512, DYNSMEM>>>(out);
}